// round 11
// baseline (speedup 1.0000x reference)
#include <cuda_runtime.h>
#include <cuda_fp16.h>

#define Bq   512
#define Tt   365
#define Ff   16
#define Hh   256
#define G4   1024
#define CLU  8       // CTAs per cluster
#define NCLU 16      // clusters -> 128 CTAs
#define MBc  32      // batch rows per cluster (2 M-tiles)
#define NT   512     // 16 warps; warp w owns 8 gate cols
#define K1T  17      // layer-1 k-tiles (272 = 16 x + 256 h1)
#define K2T  32      // layer-2 k-tiles (512 = 256 h1 + 256 h2)
#define HST  552     // h-buffer col stride (halves); 552*2=1104B, 16B-aligned
#define BUFH (MBc * HST)             // halves per buffer
#define SMEM_BYTES (2 * BUFH * 2)    // two parity buffers, fp16

// ---------------------------------------------------------------------------
// Pre-packed fp16 B fragments (m16n8k16 .col), packed col order:
//   packed col P = rank*128 + w*8 + j ;  j&3 = gate(i,f,g,o), unit = rank*32+2w+(j>>2)
//   frag idx ((kt*8 + rank)*16 + w)*32 + lane -> uint2 = 4 halves:
//   B[k0+2m][c], B[k0+2m+1][c], B[k0+2m+8][c], B[k0+2m+9][c], c = P-col of (lane>>2)
// ---------------------------------------------------------------------------
__device__ __align__(16) __half g_wb1[(Ff + Hh) * G4];
__device__ __align__(16) __half g_wb2[2 * Hh * G4];
__device__ float g_b1p[G4];
__device__ float g_b2p[G4];

__device__ __forceinline__ float sigf(float x) { return 1.0f / (1.0f + __expf(-x)); }

__device__ __forceinline__ unsigned s2u(const void* p) {
    unsigned a;
    asm("{ .reg .u64 t; cvta.to.shared.u64 t, %1; cvt.u32.u64 %0, t; }" : "=r"(a) : "l"(p));
    return a;
}
__device__ __forceinline__ void ldsm4(unsigned& a0, unsigned& a1, unsigned& a2, unsigned& a3,
                                      unsigned addr) {
    asm volatile("ldmatrix.sync.aligned.m8n8.x4.shared.b16 {%0,%1,%2,%3}, [%4];"
                 : "=r"(a0), "=r"(a1), "=r"(a2), "=r"(a3) : "r"(addr));
}
__device__ __forceinline__ void mma16816(float& d0, float& d1, float& d2, float& d3,
                                         unsigned a0, unsigned a1, unsigned a2, unsigned a3,
                                         unsigned b0, unsigned b1) {
    asm volatile("mma.sync.aligned.m16n8k16.row.col.f32.f16.f16.f32 "
                 "{%0,%1,%2,%3}, {%4,%5,%6,%7}, {%8,%9}, {%0,%1,%2,%3};"
                 : "+f"(d0), "+f"(d1), "+f"(d2), "+f"(d3)
                 : "r"(a0), "r"(a1), "r"(a2), "r"(a3), "r"(b0), "r"(b1));
}
__device__ __forceinline__ void st_cluster_h(unsigned addr, unsigned rank, unsigned short v) {
    unsigned ra;
    asm volatile("mapa.shared::cluster.u32 %0, %1, %2;" : "=r"(ra) : "r"(addr), "r"(rank));
    asm volatile("st.shared::cluster.b16 [%0], %1;" :: "r"(ra), "h"(v) : "memory");
}
__device__ __forceinline__ void cluster_sync_all() {
    asm volatile("barrier.cluster.arrive.aligned;" ::: "memory");
    asm volatile("barrier.cluster.wait.aligned;"   ::: "memory");
}

// ---------------------------------------------------------------------------
// Prep: pack B fragments in cluster/warp order + fuse biases (packed order).
// ---------------------------------------------------------------------------
__global__ void prep_kernel(const float* __restrict__ wih1, const float* __restrict__ whh1,
                            const float* __restrict__ bih1, const float* __restrict__ bhh1,
                            const float* __restrict__ wih2, const float* __restrict__ whh2,
                            const float* __restrict__ bih2, const float* __restrict__ bhh2) {
    int idx = blockIdx.x * blockDim.x + threadIdx.x;    // over K2T*8*16*32 = 131072
    int lane = idx & 31, w = (idx >> 5) & 15, r = (idx >> 9) & 7, kt = idx >> 12;
    int m = lane & 3, c = lane >> 2;
    int P = r * 128 + w * 8 + c;
    int j = P & 7, gi = j & 3;
    int oc = gi * 256 + r * 32 + 2 * w + (j >> 2);      // original torch gate-col
    int k0 = kt * 16;
    int ks[4] = {k0 + 2 * m, k0 + 2 * m + 1, k0 + 2 * m + 8, k0 + 2 * m + 9};

    if (kt < K2T) {
        __align__(8) __half h[4];
        #pragma unroll
        for (int q = 0; q < 4; ++q) {
            int k = ks[q];
            float v = (k < Hh) ? wih2[oc * Hh + k] : whh2[oc * Hh + (k - Hh)];
            h[q] = __float2half_rn(v);
        }
        *((uint2*)g_wb2 + idx) = *(const uint2*)h;
    }
    if (kt < K1T) {
        __align__(8) __half h[4];
        #pragma unroll
        for (int q = 0; q < 4; ++q) {
            int k = ks[q];
            float v = (k < Ff) ? wih1[oc * Ff + k] : whh1[oc * Hh + (k - Ff)];
            h[q] = __float2half_rn(v);
        }
        *((uint2*)g_wb1 + idx) = *(const uint2*)h;
    }
    if (idx < G4) {
        int Pb = idx;
        int jb = Pb & 7, gb = jb & 3;
        int ocb = gb * 256 + (Pb >> 7) * 32 + 2 * ((Pb >> 3) & 15) + (jb >> 2);
        g_b1p[Pb] = bih1[ocb] + bhh1[ocb];
        g_b2p[Pb] = bih2[ocb] + bhh2[ocb];
    }
}

// ---------------------------------------------------------------------------
// Fused 2-layer LSTM, 8-CTA clusters. CTA = 128 gate cols x 32 batch rows.
// h buffer cols: [0..15]=x, [16..271]=h1, [272..527]=h2; parity double-buffered.
// Update in registers via lane-pair shuffles; h pushed to all ranks via DSMEM.
// ---------------------------------------------------------------------------
__global__ void __cluster_dims__(CLU, 1, 1) __launch_bounds__(NT, 1)
lstm_kernel(const float* __restrict__ x,
            const float* __restrict__ wlin, const float* __restrict__ blin,
            float* __restrict__ out) {
    extern __shared__ __align__(16) __half buf[];   // [2][MBc][HST]

    const int tid  = threadIdx.x;
    const int lane = tid & 31;
    const int w    = tid >> 5;
    const int m    = lane & 3;
    const int g    = lane >> 2;
    unsigned rank; asm("mov.u32 %0, %%cluster_ctarank;" : "=r"(rank));
    const int clu  = blockIdx.x >> 3;
    const int b0   = clu * MBc;

    // zero both buffers
    for (int i = tid; i < 2 * BUFH; i += NT) buf[i] = __float2half_rn(0.f);

    float c1[2] = {0.f, 0.f};
    float c2[2] = {0.f, 0.f};

    // biases (packed order): this thread's cols 2m, 2m+1 within warp's 8
    const float2 bb1 = *(const float2*)&g_b1p[rank * 128 + w * 8 + 2 * m];
    const float2 bb2 = *(const float2*)&g_b2p[rank * 128 + w * 8 + 2 * m];

    const uint2* wb1 = (const uint2*)g_wb1 + ((0 * CLU + rank) * 16 + w) * 32 + lane;
    const uint2* wb2 = (const uint2*)g_wb2 + ((0 * CLU + rank) * 16 + w) * 32 + lane;
    const int KTS = CLU * 16 * 32;    // frag stride per kt = 4096 uint2

    // ldmatrix lane addressing
    const int lr  = (lane & 7) + 8 * ((lane >> 3) & 1);
    const int lc8 = (lane >> 4) * 8;
    const unsigned sbase = s2u(buf);

    // update-phase identity: rows (m&1 ? g+8 : g) + 16*mt; unit ug
    const int rrow = g + 8 * (m & 1);
    const int ug   = rank * 32 + 2 * w + (m >> 1);
    const unsigned evenm = !(m & 1);

    cluster_sync_all();   // zero-init visible cluster-wide

    int p = 0;
    for (int t = 0; t < Tt; ++t) {
        const unsigned pb  = (unsigned)p * BUFH;
        const unsigned pnb = (unsigned)(p ^ 1) * BUFH;

        // ---- stage x_t into buf[p] cols 0..15 (one value per thread) ----
        {
            int b = tid >> 4, f = tid & 15;
            buf[pb + b * HST + f] =
                __float2half_rn(__ldg(&x[((size_t)(b0 + b) * Tt + t) * Ff + f]));
        }
        __syncthreads();

        // ================= LAYER 1 gates =================
        float acc[2][4];
        #pragma unroll
        for (int mt = 0; mt < 2; ++mt) {
            acc[mt][0] = bb1.x; acc[mt][1] = bb1.y; acc[mt][2] = bb1.x; acc[mt][3] = bb1.y;
        }
        for (int kt = 0; kt < K1T; ++kt) {
            uint2 bv = __ldg(wb1 + kt * KTS);
            unsigned base = sbase + (pb + lr * HST + kt * 16 + lc8) * 2u;
            unsigned a0, a1, a2, a3, e0, e1, e2, e3;
            ldsm4(a0, a1, a2, a3, base);
            ldsm4(e0, e1, e2, e3, base + 16 * HST * 2u);
            mma16816(acc[0][0], acc[0][1], acc[0][2], acc[0][3], a0, a1, a2, a3, bv.x, bv.y);
            mma16816(acc[1][0], acc[1][1], acc[1][2], acc[1][3], e0, e1, e2, e3, bv.x, bv.y);
        }
        // ---- update 1 (in registers) ----
        #pragma unroll
        for (int mt = 0; mt < 2; ++mt) {
            float t0 = __shfl_xor_sync(0xffffffffu, acc[mt][0], 1);
            float t1 = __shfl_xor_sync(0xffffffffu, acc[mt][1], 1);
            float t2 = __shfl_xor_sync(0xffffffffu, acc[mt][2], 1);
            float t3 = __shfl_xor_sync(0xffffffffu, acc[mt][3], 1);
            float zi = evenm ? acc[mt][0] : t2;
            float zf = evenm ? acc[mt][1] : t3;
            float zg = evenm ? t0 : acc[mt][2];
            float zo = evenm ? t1 : acc[mt][3];
            c1[mt] = sigf(zf) * c1[mt] + sigf(zi) * tanhf(zg);
            float h = sigf(zo) * tanhf(c1[mt]);
            unsigned short hv = __half_as_ushort(__float2half_rn(h));
            unsigned addr = sbase + (pnb + (rrow + 16 * mt) * HST + 16 + ug) * 2u;
            #pragma unroll
            for (unsigned rr = 0; rr < CLU; ++rr) st_cluster_h(addr, rr, hv);
        }
        cluster_sync_all();   // h1_new visible in all ranks' buf[p^1]

        // ================= LAYER 2 gates =================
        #pragma unroll
        for (int mt = 0; mt < 2; ++mt) {
            acc[mt][0] = bb2.x; acc[mt][1] = bb2.y; acc[mt][2] = bb2.x; acc[mt][3] = bb2.y;
        }
        for (int kt = 0; kt < 16; ++kt) {     // h1 (new) from buf[p^1]
            uint2 bv = __ldg(wb2 + kt * KTS);
            unsigned base = sbase + (pnb + lr * HST + 16 + kt * 16 + lc8) * 2u;
            unsigned a0, a1, a2, a3, e0, e1, e2, e3;
            ldsm4(a0, a1, a2, a3, base);
            ldsm4(e0, e1, e2, e3, base + 16 * HST * 2u);
            mma16816(acc[0][0], acc[0][1], acc[0][2], acc[0][3], a0, a1, a2, a3, bv.x, bv.y);
            mma16816(acc[1][0], acc[1][1], acc[1][2], acc[1][3], e0, e1, e2, e3, bv.x, bv.y);
        }
        for (int kt = 16; kt < K2T; ++kt) {   // h2 (old) from buf[p]
            uint2 bv = __ldg(wb2 + kt * KTS);
            unsigned base = sbase + (pb + lr * HST + 272 + (kt - 16) * 16 + lc8) * 2u;
            unsigned a0, a1, a2, a3, e0, e1, e2, e3;
            ldsm4(a0, a1, a2, a3, base);
            ldsm4(e0, e1, e2, e3, base + 16 * HST * 2u);
            mma16816(acc[0][0], acc[0][1], acc[0][2], acc[0][3], a0, a1, a2, a3, bv.x, bv.y);
            mma16816(acc[1][0], acc[1][1], acc[1][2], acc[1][3], e0, e1, e2, e3, bv.x, bv.y);
        }
        // ---- update 2 ----
        #pragma unroll
        for (int mt = 0; mt < 2; ++mt) {
            float t0 = __shfl_xor_sync(0xffffffffu, acc[mt][0], 1);
            float t1 = __shfl_xor_sync(0xffffffffu, acc[mt][1], 1);
            float t2 = __shfl_xor_sync(0xffffffffu, acc[mt][2], 1);
            float t3 = __shfl_xor_sync(0xffffffffu, acc[mt][3], 1);
            float zi = evenm ? acc[mt][0] : t2;
            float zf = evenm ? acc[mt][1] : t3;
            float zg = evenm ? t0 : acc[mt][2];
            float zo = evenm ? t1 : acc[mt][3];
            c2[mt] = sigf(zf) * c2[mt] + sigf(zi) * tanhf(zg);
            float h = sigf(zo) * tanhf(c2[mt]);
            unsigned short hv = __half_as_ushort(__float2half_rn(h));
            unsigned addr = sbase + (pnb + (rrow + 16 * mt) * HST + 272 + ug) * 2u;
            #pragma unroll
            for (unsigned rr = 0; rr < CLU; ++rr) st_cluster_h(addr, rr, hv);
        }
        cluster_sync_all();   // h2_new visible

        p ^= 1;
    }

    // ================= linear head: rank -> rows rank*4..rank*4+3 =================
    if (w < 4) {
        const int row = (int)rank * 4 + w;
        float s = 0.f;
        #pragma unroll
        for (int u = lane; u < Hh; u += 32)
            s += __half2float(buf[(unsigned)p * BUFH + row * HST + 272 + u]) * __ldg(&wlin[u]);
        #pragma unroll
        for (int off = 16; off; off >>= 1) s += __shfl_xor_sync(0xffffffffu, s, off);
        if (lane == 0) out[b0 + row] = s + blin[0];
    }
}

// ---------------------------------------------------------------------------
extern "C" void kernel_launch(void* const* d_in, const int* in_sizes, int n_in,
                              void* d_out, int out_size) {
    const float* x    = (const float*)d_in[0];
    const float* wih1 = (const float*)d_in[1];
    const float* whh1 = (const float*)d_in[2];
    const float* bih1 = (const float*)d_in[3];
    const float* bhh1 = (const float*)d_in[4];
    const float* wih2 = (const float*)d_in[5];
    const float* whh2 = (const float*)d_in[6];
    const float* bih2 = (const float*)d_in[7];
    const float* bhh2 = (const float*)d_in[8];
    const float* wlin = (const float*)d_in[9];
    const float* blin = (const float*)d_in[10];
    float* out = (float*)d_out;

    static int smem_set = 0;
    if (!smem_set) {
        cudaFuncSetAttribute(lstm_kernel,
                             cudaFuncAttributeMaxDynamicSharedMemorySize, SMEM_BYTES);
        smem_set = 1;
    }

    prep_kernel<<<(K2T * CLU * 16 * 32 + 255) / 256, 256>>>(wih1, whh1, bih1, bhh1,
                                                            wih2, whh2, bih2, bhh2);
    lstm_kernel<<<NCLU * CLU, NT, SMEM_BYTES>>>(x, wlin, blin, out);
}

// round 12
// speedup vs baseline: 1.6899x; 1.6899x over previous
#include <cuda_runtime.h>
#include <cuda_fp16.h>

#define Bq   512
#define Tt   365
#define Ff   16
#define Hh   256
#define G4   1024
#define NCg  32      // CTAs (16 batch rows each)
#define MB   16      // batch rows per CTA
#define NT   512     // 16 warps; warp w owns units w*16..w*16+15 (all 4 gates)
#define K1T  17      // layer-1 k-tiles (272 = 16 x + 256 h1)
#define K2T  32      // layer-2 k-tiles (512 = 256 h1 + 256 h2)
#define HST  536     // unified buffer col stride (halves): [x 16 | h1 256 | h2 256 | pad]
#define H1OFF 16
#define H2OFF 272

typedef unsigned long long u64;

// ---------------------------------------------------------------------------
// Pre-packed fp16 B fragments (m16n8k16 .col), GATE-INTERLEAVED col order:
//   packed col P = w*64 + n ; gate = n&3 (i,f,g,o), unit = w*16 + (n>>2)
//   original torch col oc = gate*256 + unit
//   frag idx ((kt*16 + w)*4 + p)*32 + lane -> uint4 = 8 halves:
//     halves 0..3 = tile 2p  (col PA = w*64+16p+(lane>>2)): B[k0+2m],[k0+2m+1],[k0+2m+8],[k0+2m+9]
//     halves 4..7 = tile 2p+1 (col PA+8), same k rows         (m = lane&3)
// ---------------------------------------------------------------------------
__device__ __align__(16) __half g_wb1[(Ff + Hh) * G4];
__device__ __align__(16) __half g_wb2[2 * Hh * G4];
__device__ float g_b1p[G4];   // biases in packed col order
__device__ float g_b2p[G4];

__device__ __forceinline__ float sigf(float x) { return 1.0f / (1.0f + __expf(-x)); }

__device__ __forceinline__ unsigned s2u(const void* p) {
    unsigned a;
    asm("{ .reg .u64 t; cvta.to.shared.u64 t, %1; cvt.u32.u64 %0, t; }" : "=r"(a) : "l"(p));
    return a;
}
__device__ __forceinline__ void ldsm4(unsigned& a0, unsigned& a1, unsigned& a2, unsigned& a3,
                                      unsigned addr) {
    asm volatile("ldmatrix.sync.aligned.m8n8.x4.shared.b16 {%0,%1,%2,%3}, [%4];"
                 : "=r"(a0), "=r"(a1), "=r"(a2), "=r"(a3) : "r"(addr));
}
__device__ __forceinline__ void mma16816(float& d0, float& d1, float& d2, float& d3,
                                         unsigned a0, unsigned a1, unsigned a2, unsigned a3,
                                         unsigned b0, unsigned b1) {
    asm volatile("mma.sync.aligned.m16n8k16.row.col.f32.f16.f16.f32 "
                 "{%0,%1,%2,%3}, {%4,%5,%6,%7}, {%8,%9}, {%0,%1,%2,%3};"
                 : "+f"(d0), "+f"(d1), "+f"(d2), "+f"(d3)
                 : "r"(a0), "r"(a1), "r"(a2), "r"(a3), "r"(b0), "r"(b1));
}
__device__ __forceinline__ void sts16(unsigned addr, __half v) {
    asm volatile("st.shared.b16 [%0], %1;" :: "r"(addr), "h"(__half_as_ushort(v)) : "memory");
}

// ---------------------------------------------------------------------------
// Prep: pack B fragments (gate-interleaved cols) + biases in packed order.
// ---------------------------------------------------------------------------
__global__ void prep_kernel(const float* __restrict__ wih1, const float* __restrict__ whh1,
                            const float* __restrict__ bih1, const float* __restrict__ bhh1,
                            const float* __restrict__ wih2, const float* __restrict__ whh2,
                            const float* __restrict__ bih2, const float* __restrict__ bhh2) {
    int idx = blockIdx.x * blockDim.x + threadIdx.x;   // over K2T*16*4*32 = 65536
    int lane = idx & 31, p = (idx >> 5) & 3, w = (idx >> 7) & 15, kt = idx >> 11;
    int m = lane & 3, c = lane >> 2;
    int k0 = kt * 16;
    int nA = p * 16 + c, nB = nA + 8;                  // packed cols within warp
    int ocA = (nA & 3) * 256 + w * 16 + (nA >> 2);
    int ocB = (nB & 3) * 256 + w * 16 + (nB >> 2);
    int ks[4] = {k0 + 2 * m, k0 + 2 * m + 1, k0 + 2 * m + 8, k0 + 2 * m + 9};

    if (kt < K2T) {   // layer 2: K = 512 (h1 rows 0..255, h2 rows 256..511)
        __align__(16) __half h[8];
        #pragma unroll
        for (int j = 0; j < 4; ++j) {
            int k = ks[j];
            float vA = (k < Hh) ? wih2[ocA * Hh + k] : whh2[ocA * Hh + (k - Hh)];
            float vB = (k < Hh) ? wih2[ocB * Hh + k] : whh2[ocB * Hh + (k - Hh)];
            h[j]     = __float2half_rn(vA);
            h[4 + j] = __float2half_rn(vB);
        }
        *((uint4*)g_wb2 + idx) = *(const uint4*)h;
    }
    if (kt < K1T) {   // layer 1: K = 272 (x rows 0..15, h1 rows 16..271)
        __align__(16) __half h[8];
        #pragma unroll
        for (int j = 0; j < 4; ++j) {
            int k = ks[j];
            float vA = (k < Ff) ? wih1[ocA * Ff + k] : whh1[ocA * Hh + (k - Ff)];
            float vB = (k < Ff) ? wih1[ocB * Ff + k] : whh1[ocB * Hh + (k - Ff)];
            h[j]     = __float2half_rn(vA);
            h[4 + j] = __float2half_rn(vB);
        }
        *((uint4*)g_wb1 + idx) = *(const uint4*)h;
    }
    if (idx < G4) {
        int P = idx, wp = P >> 6, n = P & 63;
        int oc = (n & 3) * 256 + wp * 16 + (n >> 2);
        g_b1p[P] = bih1[oc] + bhh1[oc];
        g_b2p[P] = bih2[oc] + bhh2[oc];
    }
}

// ---------------------------------------------------------------------------
// Fused 2-layer LSTM, tensor cores, in-register gate update.
// Gate phase: warp w -> 64 packed cols (16 units x 4 gates), M=16.
// Update: shfl.xor(1) pairs lanes (i,f | g,o); cell (row, unit) per lane per nt.
// ---------------------------------------------------------------------------
__global__ void __launch_bounds__(NT, 1)
lstm_kernel(const float* __restrict__ x,
            const float* __restrict__ wlin, const float* __restrict__ blin,
            float* __restrict__ out) {
    __shared__ __align__(16) __half buf[MB * HST];   // [16 rows][x|h1|h2]

    const int tid  = threadIdx.x;
    const int lane = tid & 31;
    const int w    = tid >> 5;
    const int m    = lane & 3;
    const int g    = lane >> 2;
    const bool modd = (m & 1);
    const int b0   = blockIdx.x * MB;

    for (int i = tid; i < MB * HST; i += NT) buf[i] = __ushort_as_half(0);

    float c1[8], c2[8];
    #pragma unroll
    for (int j = 0; j < 8; ++j) { c1[j] = 0.f; c2[j] = 0.f; }

    const unsigned sbase = s2u(buf);
    const int lr  = (lane & 7) + 8 * ((lane >> 3) & 1);
    const int lc8 = (lane >> 4) * 8;
    const unsigned aBase = sbase + (unsigned)(lr * HST + lc8) * 2u;

    const uint4* wb1 = (const uint4*)g_wb1 + w * 128 + lane;   // + kt*2048 + p*32
    const uint4* wb2 = (const uint4*)g_wb2 + w * 128 + lane;

    // update identity: row = g (m even) or g+8 (m odd); unit = w*16 + 2nt + (m>>1)
    const int urow = modd ? (g + 8) : g;
    const unsigned h1addr = sbase + (unsigned)(urow * HST + H1OFF + w * 16 + (m >> 1)) * 2u;
    const unsigned h2addr = sbase + (unsigned)(urow * HST + H2OFF + w * 16 + (m >> 1)) * 2u;

    // stage x(0)
    if (tid < MB * Ff) {
        int b = tid >> 4, f = tid & 15;
        buf[b * HST + f] = __float2half_rn(__ldg(&x[((size_t)(b0 + b) * Tt) * Ff + f]));
    }
    __syncthreads();

    float acc[8][4];

    for (int t = 0; t < Tt; ++t) {
        // ================= LAYER 1 gates =================
        #pragma unroll
        for (int nt = 0; nt < 8; ++nt) {
            float2 bv = __ldg((const float2*)&g_b1p[w * 64 + 8 * nt + 2 * m]);
            acc[nt][0] = bv.x; acc[nt][1] = bv.y; acc[nt][2] = bv.x; acc[nt][3] = bv.y;
        }
        for (int kt = 0; kt < K1T; ++kt) {
            uint4 bv0 = __ldg(wb1 + kt * 2048);
            uint4 bv1 = __ldg(wb1 + kt * 2048 + 32);
            uint4 bv2 = __ldg(wb1 + kt * 2048 + 64);
            uint4 bv3 = __ldg(wb1 + kt * 2048 + 96);
            unsigned a0, a1, a2, a3;
            ldsm4(a0, a1, a2, a3, aBase + (unsigned)(kt * 16) * 2u);
            mma16816(acc[0][0], acc[0][1], acc[0][2], acc[0][3], a0, a1, a2, a3, bv0.x, bv0.y);
            mma16816(acc[1][0], acc[1][1], acc[1][2], acc[1][3], a0, a1, a2, a3, bv0.z, bv0.w);
            mma16816(acc[2][0], acc[2][1], acc[2][2], acc[2][3], a0, a1, a2, a3, bv1.x, bv1.y);
            mma16816(acc[3][0], acc[3][1], acc[3][2], acc[3][3], a0, a1, a2, a3, bv1.z, bv1.w);
            mma16816(acc[4][0], acc[4][1], acc[4][2], acc[4][3], a0, a1, a2, a3, bv2.x, bv2.y);
            mma16816(acc[5][0], acc[5][1], acc[5][2], acc[5][3], a0, a1, a2, a3, bv2.z, bv2.w);
            mma16816(acc[6][0], acc[6][1], acc[6][2], acc[6][3], a0, a1, a2, a3, bv3.x, bv3.y);
            mma16816(acc[7][0], acc[7][1], acc[7][2], acc[7][3], a0, a1, a2, a3, bv3.z, bv3.w);
        }
        __syncthreads();   // all reads of h1(old)/x done

        // ---- update 1 (registers) + write h1 ----
        #pragma unroll
        for (int nt = 0; nt < 8; ++nt) {
            float t0 = __shfl_xor_sync(0xffffffffu, acc[nt][0], 1);
            float t1 = __shfl_xor_sync(0xffffffffu, acc[nt][1], 1);
            float t2 = __shfl_xor_sync(0xffffffffu, acc[nt][2], 1);
            float t3 = __shfl_xor_sync(0xffffffffu, acc[nt][3], 1);
            float zi = modd ? t2 : acc[nt][0];
            float zf = modd ? t3 : acc[nt][1];
            float zg = modd ? acc[nt][2] : t0;
            float zo = modd ? acc[nt][3] : t1;
            c1[nt] = sigf(zf) * c1[nt] + sigf(zi) * tanhf(zg);
            float h = sigf(zo) * tanhf(c1[nt]);
            sts16(h1addr + 4u * nt, __float2half_rn(h));
        }
        __syncthreads();   // h1(new) visible

        // ================= LAYER 2 gates =================
        #pragma unroll
        for (int nt = 0; nt < 8; ++nt) {
            float2 bv = __ldg((const float2*)&g_b2p[w * 64 + 8 * nt + 2 * m]);
            acc[nt][0] = bv.x; acc[nt][1] = bv.y; acc[nt][2] = bv.x; acc[nt][3] = bv.y;
        }
        for (int kt = 0; kt < K2T; ++kt) {
            uint4 bv0 = __ldg(wb2 + kt * 2048);
            uint4 bv1 = __ldg(wb2 + kt * 2048 + 32);
            uint4 bv2 = __ldg(wb2 + kt * 2048 + 64);
            uint4 bv3 = __ldg(wb2 + kt * 2048 + 96);
            unsigned a0, a1, a2, a3;
            ldsm4(a0, a1, a2, a3, aBase + (unsigned)(H1OFF + kt * 16) * 2u);
            mma16816(acc[0][0], acc[0][1], acc[0][2], acc[0][3], a0, a1, a2, a3, bv0.x, bv0.y);
            mma16816(acc[1][0], acc[1][1], acc[1][2], acc[1][3], a0, a1, a2, a3, bv0.z, bv0.w);
            mma16816(acc[2][0], acc[2][1], acc[2][2], acc[2][3], a0, a1, a2, a3, bv1.x, bv1.y);
            mma16816(acc[3][0], acc[3][1], acc[3][2], acc[3][3], a0, a1, a2, a3, bv1.z, bv1.w);
            mma16816(acc[4][0], acc[4][1], acc[4][2], acc[4][3], a0, a1, a2, a3, bv2.x, bv2.y);
            mma16816(acc[5][0], acc[5][1], acc[5][2], acc[5][3], a0, a1, a2, a3, bv2.z, bv2.w);
            mma16816(acc[6][0], acc[6][1], acc[6][2], acc[6][3], a0, a1, a2, a3, bv3.x, bv3.y);
            mma16816(acc[7][0], acc[7][1], acc[7][2], acc[7][3], a0, a1, a2, a3, bv3.z, bv3.w);
        }
        __syncthreads();   // all reads of h1(new)/h2(old) done

        // ---- update 2 (registers) + write h2 + stage x(t+1) ----
        #pragma unroll
        for (int nt = 0; nt < 8; ++nt) {
            float t0 = __shfl_xor_sync(0xffffffffu, acc[nt][0], 1);
            float t1 = __shfl_xor_sync(0xffffffffu, acc[nt][1], 1);
            float t2 = __shfl_xor_sync(0xffffffffu, acc[nt][2], 1);
            float t3 = __shfl_xor_sync(0xffffffffu, acc[nt][3], 1);
            float zi = modd ? t2 : acc[nt][0];
            float zf = modd ? t3 : acc[nt][1];
            float zg = modd ? acc[nt][2] : t0;
            float zo = modd ? acc[nt][3] : t1;
            c2[nt] = sigf(zf) * c2[nt] + sigf(zi) * tanhf(zg);
            float h = sigf(zo) * tanhf(c2[nt]);
            sts16(h2addr + 4u * nt, __float2half_rn(h));
        }
        if (tid < MB * Ff && t + 1 < Tt) {
            int b = tid >> 4, f = tid & 15;
            buf[b * HST + f] =
                __float2half_rn(__ldg(&x[((size_t)(b0 + b) * Tt + (t + 1)) * Ff + f]));
        }
        __syncthreads();   // h2(new) + x(t+1) visible
    }

    // ================= linear head: warp w -> batch row w =================
    {
        float s = 0.f;
        #pragma unroll
        for (int u = lane; u < Hh; u += 32)
            s += __half2float(buf[w * HST + H2OFF + u]) * __ldg(&wlin[u]);
        #pragma unroll
        for (int off = 16; off; off >>= 1) s += __shfl_xor_sync(0xffffffffu, s, off);
        if (lane == 0) out[b0 + w] = s + blin[0];
    }
}

// ---------------------------------------------------------------------------
extern "C" void kernel_launch(void* const* d_in, const int* in_sizes, int n_in,
                              void* d_out, int out_size) {
    const float* x    = (const float*)d_in[0];
    const float* wih1 = (const float*)d_in[1];
    const float* whh1 = (const float*)d_in[2];
    const float* bih1 = (const float*)d_in[3];
    const float* bhh1 = (const float*)d_in[4];
    const float* wih2 = (const float*)d_in[5];
    const float* whh2 = (const float*)d_in[6];
    const float* bih2 = (const float*)d_in[7];
    const float* bhh2 = (const float*)d_in[8];
    const float* wlin = (const float*)d_in[9];
    const float* blin = (const float*)d_in[10];
    float* out = (float*)d_out;

    prep_kernel<<<(K2T * 16 * 4 * 32 + 255) / 256, 256>>>(wih1, whh1, bih1, bhh1,
                                                          wih2, whh2, bih2, bhh2);
    lstm_kernel<<<NCg, NT>>>(x, wlin, blin, out);
}